// round 5
// baseline (speedup 1.0000x reference)
#include <cuda_runtime.h>
#include <math.h>

namespace {

constexpr float EPSF = 1e-6f;
constexpr int BLOCK = 128;
constexpr int FPH = 63;           // floats per hand (21 joints * 3)

struct f3 { float x, y, z; };

__device__ __forceinline__ f3 operator+(f3 a, f3 b){ return {a.x+b.x, a.y+b.y, a.z+b.z}; }
__device__ __forceinline__ f3 operator-(f3 a, f3 b){ return {a.x-b.x, a.y-b.y, a.z-b.z}; }
__device__ __forceinline__ f3 operator*(f3 a, float s){ return {a.x*s, a.y*s, a.z*s}; }
__device__ __forceinline__ float dotf(f3 a, f3 b){ return a.x*b.x + a.y*b.y + a.z*b.z; }
__device__ __forceinline__ f3 crossf(f3 a, f3 b){
    return { a.y*b.z - a.z*b.y, a.z*b.x - a.x*b.z, a.x*b.y - a.y*b.x };
}
__device__ __forceinline__ f3 unitv(f3 v){
    float n = sqrtf(dotf(v,v)) + EPSF;
    float inv = 1.0f / n;
    return v * inv;
}
__device__ __forceinline__ float clip1(float x){
    return fminf(fmaxf(x, -1.0f + EPSF), 1.0f - EPSF);
}

struct mat3 { f3 r0, r1, r2; };
__device__ __forceinline__ f3 mmul(const mat3& R, f3 v){
    return { dotf(R.r0, v), dotf(R.r1, v), dotf(R.r2, v) };
}
__device__ __forceinline__ mat3 rodrigues(float x, float y, float z, float c, float s){
    float C = 1.0f - c;
    mat3 R;
    R.r0 = { c + x*x*C,   x*y*C - z*s, x*z*C + y*s };
    R.r1 = { y*x*C + z*s, c + y*y*C,   y*z*C - x*s };
    R.r2 = { z*x*C - y*s, z*y*C + x*s, c + z*z*C   };
    return R;
}
__device__ __forceinline__ mat3 rotmat(f3 axis, float th){
    float n = sqrtf(dotf(axis,axis)) + EPSF;
    float inv = 1.0f / n;
    return rodrigues(axis.x*inv, axis.y*inv, axis.z*inv, cosf(th), sinf(th));
}

// getrot: pick rotation by +dif or -dif about axis that best aligns startv with endv.
__device__ __forceinline__ mat3 getrot(float angleP, float angle, float flexRatio,
                                       f3 axis, f3 startv, f3 endv){
    const float thr = 3.1415926f / 180.0f * 120.0f;
    float ang = (angle > thr) ? (3.1415926f - angle) : angle;
    float dif = fmaxf(ang - angleP, 0.0f) * flexRatio;
    float n   = sqrtf(dotf(axis,axis)) + EPSF;
    float inv = 1.0f / n;
    float x = axis.x*inv, y = axis.y*inv, z = axis.z*inv;
    float c = cosf(dif), s = sinf(dif);
    mat3 R0 = rodrigues(x, y, z, c,  s);
    mat3 R1 = rodrigues(x, y, z, c, -s);
    f3 v0 = unitv(mmul(R0, startv));
    f3 v1 = unitv(mmul(R1, startv));
    bool m0 = fabsf(dotf(v0, endv)) > fabsf(dotf(v1, endv));
    return m0 ? R0 : R1;
}

// Smallest eigenvector of symmetric 3x3 (sign-agnostic — caller uses dist*n).
__device__ __forceinline__ f3 min_evec(float a00, float a01, float a02,
                                       float a11, float a12, float a22){
    float p1 = a01*a01 + a02*a02 + a12*a12;
    float q  = (a00 + a11 + a22) * (1.0f/3.0f);
    float b00 = a00 - q, b11 = a11 - q, b22 = a22 - q;
    float p2 = b00*b00 + b11*b11 + b22*b22 + 2.0f*p1;
    float lam;
    if (p2 <= 1e-24f){
        lam = q;   // (near-)scalar matrix; eigenvector degenerate, fallback below
    } else {
        float p   = sqrtf(p2 * (1.0f/6.0f));
        float inv = 1.0f / p;
        float c00 = b00*inv, c01 = a01*inv, c02 = a02*inv;
        float c11 = b11*inv, c12 = a12*inv, c22 = b22*inv;
        float detB = c00*(c11*c22 - c12*c12)
                   - c01*(c01*c22 - c12*c02)
                   + c02*(c01*c12 - c11*c02);
        float r = 0.5f * detB;
        r = fminf(fmaxf(r, -1.0f), 1.0f);
        float phi = acosf(r) * (1.0f/3.0f);
        lam = q + 2.0f * p * cosf(phi + 2.0943951023931953f);   // smallest root
    }
    float m00 = a00 - lam, m11 = a11 - lam, m22 = a22 - lam;
    f3 r0 = { m00, a01, a02 };
    f3 r1 = { a01, m11, a12 };
    f3 r2 = { a02, a12, m22 };
    f3 c01v = crossf(r0, r1);
    f3 c02v = crossf(r0, r2);
    f3 c12v = crossf(r1, r2);
    float n01 = dotf(c01v, c01v), n02 = dotf(c02v, c02v), n12 = dotf(c12v, c12v);
    f3 best = c01v; float nb = n01;
    if (n02 > nb){ best = c02v; nb = n02; }
    if (n12 > nb){ best = c12v; nb = n12; }
    if (nb < 1e-32f) return {0.0f, 0.0f, 1.0f};
    float s = rsqrtf(nb);
    return best * s;
}

__device__ __forceinline__ f3 palm_norm(const f3* j, int i){
    const int MCPc[5] = {1, 4, 10, 7, 13};
    f3 w = j[0];
    f3 a, b;
    if (i < 4){ a = j[MCPc[i]] - w; b = j[MCPc[(i+1)%4]] - w; }
    else      { a = j[13] - w;      b = j[1] - w; }
    return unitv(crossf(a, b));
}

__device__ __forceinline__ void planarize(f3* j){
    const int JI[5][4] = {{1,2,3,17},{4,5,6,18},{10,11,12,19},{7,8,9,20},{13,14,15,16}};
    #pragma unroll
    for (int f = 0; f < 5; ++f){
        f3 p0 = j[JI[f][0]], p1 = j[JI[f][1]], p2 = j[JI[f][2]], p3 = j[JI[f][3]];
        f3 c = (p0 + p1 + p2 + p3) * 0.25f;
        f3 d0 = p0 - c, d1 = p1 - c, d2 = p2 - c, d3 = p3 - c;
        float a00 = d0.x*d0.x + d1.x*d1.x + d2.x*d2.x + d3.x*d3.x;
        float a01 = d0.x*d0.y + d1.x*d1.y + d2.x*d2.y + d3.x*d3.y;
        float a02 = d0.x*d0.z + d1.x*d1.z + d2.x*d2.z + d3.x*d3.z;
        float a11 = d0.y*d0.y + d1.y*d1.y + d2.y*d2.y + d3.y*d3.y;
        float a12 = d0.y*d0.z + d1.y*d1.z + d2.y*d2.z + d3.y*d3.z;
        float a22 = d0.z*d0.z + d1.z*d1.z + d2.z*d2.z + d3.z*d3.z;
        f3 n = min_evec(a00, a01, a02, a11, a12, a22);
        float nd = dotf(n, c);
        float t;
        t = dotf(p0, n) - nd; p0 = p0 - n*t;
        t = dotf(p1, n) - nd; p1 = p1 - n*t;
        t = dotf(p2, n) - nd; p2 = p2 - n*t;
        t = dotf(p3, n) - nd; p3 = p3 - n*t;
        j[JI[f][0]] = p0; j[JI[f][1]] = p1; j[JI[f][2]] = p2; j[JI[f][3]] = p3;
    }
}

__device__ __forceinline__ void abduction(f3* j){
    const int   MCPc[5] = {1, 4, 10, 7, 13};
    const int   PIPc[5] = {2, 5, 11, 8, 14};
    const int   CH[5][3] = {{2,3,17},{5,6,18},{11,12,19},{8,9,20},{14,15,16}};
    const float RECT[5] = {0.189f, 0.1331f, -0.1491f, 0.0347f, 0.0f};
    const float angleP = 0.34906585f;   // pi/9 (fp32 of jnp.pi/9)
    #pragma unroll
    for (int i = 0; i < 5; ++i){
        f3 palm = palm_norm(j, i);
        f3 mcp = j[MCPc[i]], pip = j[PIPc[i]], w = j[0];
        float vd   = -dotf(mcp, palm);
        float dist = dotf(pip, palm) + vd;
        f3 projpip = pip - palm * dist;
        f3 mp = mcp - pip;
        float dis  = sqrtf(dotf(mp, mp));
        f3 pm = projpip - mcp;
        float flex = sqrtf(dotf(pm, pm)) / (dis + EPSF);
        flex = (flex < 0.3f) ? 0.0f : flex;
        f3 wristmcp = unitv(mcp - w);
        f3 mcpproj  = unitv(projpip - mcp);
        f3 mcppip   = unitv(pip - mcp);
        bool overflex = acosf(clip1(dotf(wristmcp, mcppip))) > 1.57f;  // 3.14/2
        mat3 Rr = rotmat(palm, RECT[i]);
        f3 rect = mmul(Rr, wristmcp);
        float ang = acosf(clip1(dotf(rect, mcpproj)));
        if (overflex) ang = 0.0f;
        mat3 R = getrot(angleP, ang, flex, palm, mcpproj, wristmcp);
        #pragma unroll
        for (int k = 0; k < 3; ++k){
            int ch = CH[i][k];
            f3 v = j[ch] - mcp;
            j[ch] = mmul(R, v) + mcp;
        }
    }
}

__device__ __forceinline__ void plane_rotation(f3* j){
    const int MCPc[4] = {1, 4, 10, 7};
    const int PIPc[4] = {2, 5, 11, 8};
    const int DIPc[4] = {3, 6, 12, 9};
    const int REST[4][2] = {{3,17},{6,18},{12,19},{9,20}};
    const float angleN = 0.34906585f;   // pi/9
    #pragma unroll
    for (int i = 0; i < 4; ++i){
        f3 mcp = j[MCPc[i]], pip = j[PIPc[i]], dip = j[DIPc[i]];
        f3 mcppip = unitv(pip - mcp);
        f3 pipdip = unitv(dip - pip);
        bool maskline = fabsf(dotf(mcppip, pipdip)) > 0.95f;
        f3 cdir = unitv(crossf(mcppip, pipdip));
        f3 wm   = unitv(mcp - j[0]);
        f3 stdv = unitv(crossf(wm, palm_norm(j, i)));
        float ang = acosf(clip1(dotf(cdir, stdv)));
        if (maskline) ang = 0.0f;
        mat3 R = getrot(angleN, ang, 1.0f, mcppip, cdir, stdv);
        f3 pivot = pip;   // PR_CHILDREN[i][0] == PIP, not modified
        #pragma unroll
        for (int k = 0; k < 2; ++k){
            int ch = REST[i][k];
            f3 v = j[ch] - pivot;
            j[ch] = mmul(R, v) + pivot;
        }
    }
}

__global__ void __launch_bounds__(BLOCK)
hand_legitimize_kernel(const float* __restrict__ in, float* __restrict__ out, int N){
    __shared__ float s[BLOCK * FPH];
    const int tid = threadIdx.x;
    const int base = blockIdx.x * (BLOCK * FPH);
    const int total = N * FPH;

    // cooperative coalesced load
    #pragma unroll
    for (int k = tid; k < BLOCK * FPH; k += BLOCK){
        int g = base + k;
        s[k] = (g < total) ? in[g] : 0.0f;
    }
    __syncthreads();

    const int h = blockIdx.x * BLOCK + tid;
    if (h < N){
        f3 j[21];
        #pragma unroll
        for (int q = 0; q < 21; ++q){
            j[q].x = s[tid*FPH + 3*q + 0];
            j[q].y = s[tid*FPH + 3*q + 1];
            j[q].z = s[tid*FPH + 3*q + 2];
        }

        planarize(j);
        abduction(j);
        plane_rotation(j);
        planarize(j);

        #pragma unroll
        for (int q = 0; q < 21; ++q){
            s[tid*FPH + 3*q + 0] = j[q].x;
            s[tid*FPH + 3*q + 1] = j[q].y;
            s[tid*FPH + 3*q + 2] = j[q].z;
        }
    }
    __syncthreads();

    // cooperative coalesced store
    #pragma unroll
    for (int k = tid; k < BLOCK * FPH; k += BLOCK){
        int g = base + k;
        if (g < total) out[g] = s[k];
    }
}

} // namespace

extern "C" void kernel_launch(void* const* d_in, const int* in_sizes, int n_in,
                              void* d_out, int out_size){
    const float* joints = (const float*)d_in[0];
    float* out = (float*)d_out;
    int N = in_sizes[0] / FPH;
    int blocks = (N + BLOCK - 1) / BLOCK;
    hand_legitimize_kernel<<<blocks, BLOCK>>>(joints, out, N);
}

// round 6
// speedup vs baseline: 1.2568x; 1.2568x over previous
#include <cuda_runtime.h>
#include <math.h>
#include <stdint.h>

namespace {

constexpr float EPSF = 1e-6f;
constexpr int BLOCK = 128;
constexpr int FPH = 63;           // floats per hand (21 joints * 3)

struct f3 { float x, y, z; };

__device__ __forceinline__ f3 operator+(f3 a, f3 b){ return {a.x+b.x, a.y+b.y, a.z+b.z}; }
__device__ __forceinline__ f3 operator-(f3 a, f3 b){ return {a.x-b.x, a.y-b.y, a.z-b.z}; }
__device__ __forceinline__ f3 operator*(f3 a, float s){ return {a.x*s, a.y*s, a.z*s}; }
__device__ __forceinline__ float dotf(f3 a, f3 b){ return a.x*b.x + a.y*b.y + a.z*b.z; }
__device__ __forceinline__ f3 crossf(f3 a, f3 b){
    return { a.y*b.z - a.z*b.y, a.z*b.x - a.x*b.z, a.x*b.y - a.y*b.x };
}
__device__ __forceinline__ f3 unitv(f3 v){
    float n = sqrtf(dotf(v,v)) + EPSF;
    return v * (1.0f / n);
}
__device__ __forceinline__ float clip1(float x){
    return fminf(fmaxf(x, -1.0f + EPSF), 1.0f - EPSF);
}

struct mat3 { f3 r0, r1, r2; };
__device__ __forceinline__ f3 mmul(const mat3& R, f3 v){
    return { dotf(R.r0, v), dotf(R.r1, v), dotf(R.r2, v) };
}
__device__ __forceinline__ f3 mmulT(const mat3& R, f3 v){
    return { R.r0.x*v.x + R.r1.x*v.y + R.r2.x*v.z,
             R.r0.y*v.x + R.r1.y*v.y + R.r2.y*v.z,
             R.r0.z*v.x + R.r1.z*v.y + R.r2.z*v.z };
}
__device__ __forceinline__ mat3 rodrigues(float x, float y, float z, float c, float s){
    float C = 1.0f - c;
    mat3 R;
    R.r0 = { c + x*x*C,   x*y*C - z*s, x*z*C + y*s };
    R.r1 = { y*x*C + z*s, c + y*y*C,   y*z*C - x*s };
    R.r2 = { z*x*C - y*s, z*y*C + x*s, c + z*z*C   };
    return R;
}

// ---- opaque shared-memory joint access (keeps joints OUT of registers) ----
__device__ __forceinline__ uint32_t smem_u32(const void* p){
    uint32_t a;
    asm("{ .reg .u64 t; cvta.to.shared.u64 t, %1; cvt.u32.u64 %0, t; }" : "=r"(a) : "l"(p));
    return a;
}
__device__ __forceinline__ f3 ldj(uint32_t jb, int q){
    f3 v; uint32_t a = jb + 12u * (uint32_t)q;
    asm volatile("ld.shared.f32 %0, [%3];\n\t"
                 "ld.shared.f32 %1, [%3+4];\n\t"
                 "ld.shared.f32 %2, [%3+8];"
                 : "=f"(v.x), "=f"(v.y), "=f"(v.z) : "r"(a));
    return v;
}
__device__ __forceinline__ void stj(uint32_t jb, int q, f3 v){
    uint32_t a = jb + 12u * (uint32_t)q;
    asm volatile("st.shared.f32 [%0], %1;\n\t"
                 "st.shared.f32 [%0+4], %2;\n\t"
                 "st.shared.f32 [%0+8], %3;"
                 :: "r"(a), "f"(v.x), "f"(v.y), "f"(v.z) : "memory");
}

// getrot: build R(+dif); R(-dif) = R^T. Pick whichever best aligns startv->endv.
struct rotsel { mat3 R; bool flip; };
__device__ __forceinline__ rotsel getrot(float angleP, float angle, float flexRatio,
                                         f3 axis, f3 startv, f3 endv){
    float ang = (angle > 2.0943951f) ? (3.1415926f - angle) : angle;
    float dif = fmaxf(ang - angleP, 0.0f) * flexRatio;
    float n   = sqrtf(dotf(axis,axis)) + EPSF;
    float inv = 1.0f / n;
    float s, c;
    sincosf(dif, &s, &c);
    mat3 R = rodrigues(axis.x*inv, axis.y*inv, axis.z*inv, c, s);
    f3 v0 = unitv(mmul(R, startv));
    f3 v1 = unitv(mmulT(R, startv));
    bool use0 = fabsf(dotf(v0, endv)) > fabsf(dotf(v1, endv));
    return { R, !use0 };
}
__device__ __forceinline__ f3 applyrot(const rotsel& rs, f3 v){
    return rs.flip ? mmulT(rs.R, v) : mmul(rs.R, v);
}

// eigenvector candidate for (A - lam I): largest cross product of rows
__device__ __forceinline__ bool evec_of(float a00, float a01, float a02,
                                        float a11, float a12, float a22,
                                        float lam, f3* out){
    f3 r0 = { a00 - lam, a01, a02 };
    f3 r1 = { a01, a11 - lam, a12 };
    f3 r2 = { a02, a12, a22 - lam };
    f3 c01 = crossf(r0, r1);
    f3 c02 = crossf(r0, r2);
    f3 c12 = crossf(r1, r2);
    float n01 = dotf(c01,c01), n02 = dotf(c02,c02), n12 = dotf(c12,c12);
    f3 best = c01; float nb = n01;
    if (n02 > nb){ best = c02; nb = n02; }
    if (n12 > nb){ best = c12; nb = n12; }
    if (nb < 1e-32f) return false;
    *out = best * rsqrtf(nb);
    return true;
}

// Smallest eigenvector of symmetric 3x3, Cardano + one Rayleigh refinement.
__device__ __forceinline__ f3 min_evec(float a00, float a01, float a02,
                                       float a11, float a12, float a22){
    float p1 = a01*a01 + a02*a02 + a12*a12;
    float q  = (a00 + a11 + a22) * (1.0f/3.0f);
    float b00 = a00 - q, b11 = a11 - q, b22 = a22 - q;
    float p2 = b00*b00 + b11*b11 + b22*b22 + 2.0f*p1;
    float lam;
    if (p2 <= 1e-24f){
        lam = q;
    } else {
        float p   = sqrtf(p2 * (1.0f/6.0f));
        float inv = 1.0f / p;
        float c00 = b00*inv, c01 = a01*inv, c02 = a02*inv;
        float c11 = b11*inv, c12 = a12*inv, c22 = b22*inv;
        float detB = c00*(c11*c22 - c12*c12)
                   - c01*(c01*c22 - c12*c02)
                   + c02*(c01*c12 - c11*c02);
        float r = fminf(fmaxf(0.5f * detB, -1.0f), 1.0f);
        float phi = acosf(r) * (1.0f/3.0f);
        lam = q + 2.0f * p * cosf(phi + 2.0943951023931953f);
    }
    f3 v = {0.0f, 0.0f, 1.0f};
    if (!evec_of(a00,a01,a02,a11,a12,a22, lam, &v)) return v;
    // Rayleigh refinement: lam2 = v^T A v, re-extract.
    f3 Av = { a00*v.x + a01*v.y + a02*v.z,
              a01*v.x + a11*v.y + a12*v.z,
              a02*v.x + a12*v.y + a22*v.z };
    float lam2 = dotf(v, Av);
    f3 v2;
    if (evec_of(a00,a01,a02,a11,a12,a22, lam2, &v2)) return v2;
    return v;
}

__device__ __forceinline__ void planarize(uint32_t jb){
    const int JI[5][4] = {{1,2,3,17},{4,5,6,18},{10,11,12,19},{7,8,9,20},{13,14,15,16}};
    #pragma unroll
    for (int f = 0; f < 5; ++f){
        f3 p0 = ldj(jb, JI[f][0]), p1 = ldj(jb, JI[f][1]);
        f3 p2 = ldj(jb, JI[f][2]), p3 = ldj(jb, JI[f][3]);
        f3 c = (p0 + p1 + p2 + p3) * 0.25f;
        f3 d0 = p0 - c, d1 = p1 - c, d2 = p2 - c, d3 = p3 - c;
        float a00 = d0.x*d0.x + d1.x*d1.x + d2.x*d2.x + d3.x*d3.x;
        float a01 = d0.x*d0.y + d1.x*d1.y + d2.x*d2.y + d3.x*d3.y;
        float a02 = d0.x*d0.z + d1.x*d1.z + d2.x*d2.z + d3.x*d3.z;
        float a11 = d0.y*d0.y + d1.y*d1.y + d2.y*d2.y + d3.y*d3.y;
        float a12 = d0.y*d0.z + d1.y*d1.z + d2.y*d2.z + d3.y*d3.z;
        float a22 = d0.z*d0.z + d1.z*d1.z + d2.z*d2.z + d3.z*d3.z;
        f3 n = min_evec(a00, a01, a02, a11, a12, a22);
        float nd = dotf(n, c);
        float t;
        t = dotf(p0, n) - nd; stj(jb, JI[f][0], p0 - n*t);
        t = dotf(p1, n) - nd; stj(jb, JI[f][1], p1 - n*t);
        t = dotf(p2, n) - nd; stj(jb, JI[f][2], p2 - n*t);
        t = dotf(p3, n) - nd; stj(jb, JI[f][3], p3 - n*t);
    }
}

// palm normals (invariant across abduction + plane_rotation: wrist & MCPs never move)
__device__ __forceinline__ void palm_norms(uint32_t jb, f3 w, f3* palms){
    f3 m0 = ldj(jb, 1), m1 = ldj(jb, 4), m2 = ldj(jb, 10), m3 = ldj(jb, 7), m4 = ldj(jb, 13);
    palms[0] = unitv(crossf(m0 - w, m1 - w));
    palms[1] = unitv(crossf(m1 - w, m2 - w));
    palms[2] = unitv(crossf(m2 - w, m3 - w));
    palms[3] = unitv(crossf(m3 - w, m0 - w));
    palms[4] = unitv(crossf(m4 - w, m0 - w));
}

__device__ __forceinline__ void abduction(uint32_t jb, const f3* palms, f3 w){
    const int   MCPc[5] = {1, 4, 10, 7, 13};
    const int   PIPc[5] = {2, 5, 11, 8, 14};
    const int   CH[5][3] = {{2,3,17},{5,6,18},{11,12,19},{8,9,20},{14,15,16}};
    // cos/sin of RECTIFY angles (constants)
    const float RC[5] = {0.98219260f, 0.99115527f, 0.98890519f, 0.99939801f, 1.0f};
    const float RS[5] = {0.18787680f, 0.13270736f, -0.14854818f, 0.03469304f, 0.0f};
    const float angleP = 0.34906585f;   // pi/9
    #pragma unroll
    for (int i = 0; i < 5; ++i){
        f3 palm = palms[i];
        f3 mcp = ldj(jb, MCPc[i]);
        f3 pip = ldj(jb, PIPc[i]);
        float vd   = -dotf(mcp, palm);
        float dist = dotf(pip, palm) + vd;
        f3 projpip = pip - palm * dist;
        f3 mp = mcp - pip;
        float dis  = sqrtf(dotf(mp, mp));
        f3 pm = projpip - mcp;
        float flex = sqrtf(dotf(pm, pm)) / (dis + EPSF);
        flex = (flex < 0.3f) ? 0.0f : flex;
        f3 wristmcp = unitv(mcp - w);
        f3 mcpproj  = unitv(projpip - mcp);
        f3 mcppip   = unitv(pip - mcp);
        // acos(clip(d)) > 1.57  <=>  clip(d) < cos(1.57)
        bool overflex = clip1(dotf(wristmcp, mcppip)) < 7.9632671e-4f;
        float pn  = sqrtf(dotf(palm,palm)) + EPSF;
        float pni = 1.0f / pn;
        mat3 Rr = rodrigues(palm.x*pni, palm.y*pni, palm.z*pni, RC[i], RS[i]);
        f3 rect = mmul(Rr, wristmcp);
        float ang = acosf(clip1(dotf(rect, mcpproj)));
        if (overflex) ang = 0.0f;
        rotsel rs = getrot(angleP, ang, flex, palm, mcpproj, wristmcp);
        #pragma unroll
        for (int k = 0; k < 3; ++k){
            int ch = CH[i][k];
            f3 v = ldj(jb, ch) - mcp;
            stj(jb, ch, applyrot(rs, v) + mcp);
        }
    }
}

__device__ __forceinline__ void plane_rotation(uint32_t jb, const f3* palms, f3 w){
    const int MCPc[4] = {1, 4, 10, 7};
    const int PIPc[4] = {2, 5, 11, 8};
    const int DIPc[4] = {3, 6, 12, 9};
    const int REST[4][2] = {{3,17},{6,18},{12,19},{9,20}};
    const float angleN = 0.34906585f;   // pi/9
    #pragma unroll
    for (int i = 0; i < 4; ++i){
        f3 mcp = ldj(jb, MCPc[i]);
        f3 pip = ldj(jb, PIPc[i]);
        f3 dip = ldj(jb, DIPc[i]);
        f3 mcppip = unitv(pip - mcp);
        f3 pipdip = unitv(dip - pip);
        bool maskline = fabsf(dotf(mcppip, pipdip)) > 0.95f;
        f3 cdir = unitv(crossf(mcppip, pipdip));
        f3 wm   = unitv(mcp - w);
        f3 stdv = unitv(crossf(wm, palms[i]));
        float ang = acosf(clip1(dotf(cdir, stdv)));
        if (maskline) ang = 0.0f;
        rotsel rs = getrot(angleN, ang, 1.0f, mcppip, cdir, stdv);
        f3 pivot = pip;   // PR child[0] == PIP, unmodified
        #pragma unroll
        for (int k = 0; k < 2; ++k){
            int ch = REST[i][k];
            f3 v = ldj(jb, ch) - pivot;
            stj(jb, ch, applyrot(rs, v) + pivot);
        }
    }
}

__global__ void __launch_bounds__(BLOCK, 4)
hand_legitimize_kernel(const float* __restrict__ in, float* __restrict__ out, int N){
    __shared__ float s[BLOCK * FPH];
    const int tid = threadIdx.x;
    const int base = blockIdx.x * (BLOCK * FPH);
    const int total = N * FPH;

    // cooperative coalesced load
    #pragma unroll
    for (int k = tid; k < BLOCK * FPH; k += BLOCK){
        int g = base + k;
        s[k] = (g < total) ? in[g] : 0.0f;
    }
    __syncthreads();

    const int h = blockIdx.x * BLOCK + tid;
    if (h < N){
        uint32_t jb = smem_u32(s) + (uint32_t)tid * (FPH * 4u);
        planarize(jb);
        f3 w = ldj(jb, 0);
        f3 palms[5];
        palm_norms(jb, w, palms);
        abduction(jb, palms, w);
        plane_rotation(jb, palms, w);
        planarize(jb);
    }
    __syncthreads();

    // cooperative coalesced store
    #pragma unroll
    for (int k = tid; k < BLOCK * FPH; k += BLOCK){
        int g = base + k;
        if (g < total) out[g] = s[k];
    }
}

} // namespace

extern "C" void kernel_launch(void* const* d_in, const int* in_sizes, int n_in,
                              void* d_out, int out_size){
    const float* joints = (const float*)d_in[0];
    float* out = (float*)d_out;
    int N = in_sizes[0] / FPH;
    int blocks = (N + BLOCK - 1) / BLOCK;
    hand_legitimize_kernel<<<blocks, BLOCK>>>(joints, out, N);
}

// round 7
// speedup vs baseline: 1.6592x; 1.3202x over previous
#include <cuda_runtime.h>
#include <math.h>
#include <stdint.h>

namespace {

constexpr float EPSF = 1e-6f;
constexpr int BLOCK = 128;
constexpr int FPH = 63;           // floats per hand (21 joints * 3)

struct f3 { float x, y, z; };

__device__ __forceinline__ f3 operator+(f3 a, f3 b){ return {a.x+b.x, a.y+b.y, a.z+b.z}; }
__device__ __forceinline__ f3 operator-(f3 a, f3 b){ return {a.x-b.x, a.y-b.y, a.z-b.z}; }
__device__ __forceinline__ f3 operator*(f3 a, float s){ return {a.x*s, a.y*s, a.z*s}; }
__device__ __forceinline__ float dotf(f3 a, f3 b){ return a.x*b.x + a.y*b.y + a.z*b.z; }
__device__ __forceinline__ f3 crossf(f3 a, f3 b){
    return { a.y*b.z - a.z*b.y, a.z*b.x - a.x*b.z, a.x*b.y - a.y*b.x };
}
__device__ __forceinline__ f3 unitv(f3 v){
    float n = sqrtf(dotf(v,v)) + EPSF;
    return v * (1.0f / n);
}
__device__ __forceinline__ float clip1(float x){
    return fminf(fmaxf(x, -1.0f + EPSF), 1.0f - EPSF);
}

struct mat3 { f3 r0, r1, r2; };
__device__ __forceinline__ f3 mmul(const mat3& R, f3 v){
    return { dotf(R.r0, v), dotf(R.r1, v), dotf(R.r2, v) };
}
__device__ __forceinline__ f3 mmulT(const mat3& R, f3 v){
    return { R.r0.x*v.x + R.r1.x*v.y + R.r2.x*v.z,
             R.r0.y*v.x + R.r1.y*v.y + R.r2.y*v.z,
             R.r0.z*v.x + R.r1.z*v.y + R.r2.z*v.z };
}
__device__ __forceinline__ mat3 rodrigues(float x, float y, float z, float c, float s){
    float C = 1.0f - c;
    mat3 R;
    R.r0 = { c + x*x*C,   x*y*C - z*s, x*z*C + y*s };
    R.r1 = { y*x*C + z*s, c + y*y*C,   y*z*C - x*s };
    R.r2 = { z*x*C - y*s, z*y*C + x*s, c + z*z*C   };
    return R;
}

// ---- opaque shared-memory joint access (keeps joints OUT of registers) ----
__device__ __forceinline__ uint32_t smem_u32(const void* p){
    uint32_t a;
    asm("{ .reg .u64 t; cvta.to.shared.u64 t, %1; cvt.u32.u64 %0, t; }" : "=r"(a) : "l"(p));
    return a;
}
__device__ __forceinline__ f3 ldj(uint32_t jb, int q){
    f3 v; uint32_t a = jb + 12u * (uint32_t)q;
    asm volatile("ld.shared.f32 %0, [%3];\n\t"
                 "ld.shared.f32 %1, [%3+4];\n\t"
                 "ld.shared.f32 %2, [%3+8];"
                 : "=f"(v.x), "=f"(v.y), "=f"(v.z) : "r"(a));
    return v;
}
__device__ __forceinline__ void stj(uint32_t jb, int q, f3 v){
    uint32_t a = jb + 12u * (uint32_t)q;
    asm volatile("st.shared.f32 [%0], %1;\n\t"
                 "st.shared.f32 [%0+4], %2;\n\t"
                 "st.shared.f32 [%0+8], %3;"
                 :: "r"(a), "f"(v.x), "f"(v.y), "f"(v.z) : "memory");
}

// palm normal for finger i (wrist & MCPs are invariant during abduction/plane_rotation)
__device__ __forceinline__ f3 palm_norm(uint32_t jb, int i){
    const int MCPc[5] = {1, 4, 10, 7, 13};
    f3 w = ldj(jb, 0);
    f3 a, b;
    if (i < 4){ a = ldj(jb, MCPc[i]) - w; b = ldj(jb, MCPc[(i+1)&3]) - w; }
    else      { a = ldj(jb, 13) - w;      b = ldj(jb, 1) - w; }
    return unitv(crossf(a, b));
}

// getrot: build R(+dif); R(-dif) = R^T. ||R*s|| == ||R^T*s||, so the
// reference's unit() calls cancel in the comparison — compare raw dots.
struct rotsel { mat3 R; bool flip; };
__device__ __forceinline__ rotsel getrot(float angleP, float angle, float flexRatio,
                                         f3 axis, f3 startv, f3 endv){
    float ang = (angle > 2.0943951f) ? (3.1415926f - angle) : angle;
    float dif = fmaxf(ang - angleP, 0.0f) * flexRatio;
    float n   = sqrtf(dotf(axis,axis)) + EPSF;
    float inv = 1.0f / n;
    float s, c;
    sincosf(dif, &s, &c);
    mat3 R = rodrigues(axis.x*inv, axis.y*inv, axis.z*inv, c, s);
    bool use0 = fabsf(dotf(mmul(R, startv), endv)) > fabsf(dotf(mmulT(R, startv), endv));
    return { R, !use0 };
}
__device__ __forceinline__ f3 applyrot(const rotsel& rs, f3 v){
    return rs.flip ? mmulT(rs.R, v) : mmul(rs.R, v);
}

// eigenvector candidate for (A - lam I): largest cross product of rows
__device__ __forceinline__ bool evec_of(float a00, float a01, float a02,
                                        float a11, float a12, float a22,
                                        float lam, f3* out){
    f3 r0 = { a00 - lam, a01, a02 };
    f3 r1 = { a01, a11 - lam, a12 };
    f3 r2 = { a02, a12, a22 - lam };
    f3 c01 = crossf(r0, r1);
    f3 c02 = crossf(r0, r2);
    f3 c12 = crossf(r1, r2);
    float n01 = dotf(c01,c01), n02 = dotf(c02,c02), n12 = dotf(c12,c12);
    f3 best = c01; float nb = n01;
    if (n02 > nb){ best = c02; nb = n02; }
    if (n12 > nb){ best = c12; nb = n12; }
    if (nb < 1e-32f) return false;
    *out = best * rsqrtf(nb);
    return true;
}

// Smallest eigenvector of symmetric 3x3, Cardano + one Rayleigh refinement.
__device__ __forceinline__ f3 min_evec(float a00, float a01, float a02,
                                       float a11, float a12, float a22){
    float p1 = a01*a01 + a02*a02 + a12*a12;
    float q  = (a00 + a11 + a22) * (1.0f/3.0f);
    float b00 = a00 - q, b11 = a11 - q, b22 = a22 - q;
    float p2 = b00*b00 + b11*b11 + b22*b22 + 2.0f*p1;
    float lam;
    if (p2 <= 1e-24f){
        lam = q;
    } else {
        float p   = sqrtf(p2 * (1.0f/6.0f));
        float inv = 1.0f / p;
        float c00 = b00*inv, c01 = a01*inv, c02 = a02*inv;
        float c11 = b11*inv, c12 = a12*inv, c22 = b22*inv;
        float detB = c00*(c11*c22 - c12*c12)
                   - c01*(c01*c22 - c12*c02)
                   + c02*(c01*c12 - c11*c02);
        float r = fminf(fmaxf(0.5f * detB, -1.0f), 1.0f);
        float phi = acosf(r) * (1.0f/3.0f);
        lam = q + 2.0f * p * cosf(phi + 2.0943951023931953f);
    }
    f3 v = {0.0f, 0.0f, 1.0f};
    if (!evec_of(a00,a01,a02,a11,a12,a22, lam, &v)) return v;
    // Rayleigh refinement: lam2 = v^T A v, re-extract.
    f3 Av = { a00*v.x + a01*v.y + a02*v.z,
              a01*v.x + a11*v.y + a12*v.z,
              a02*v.x + a12*v.y + a22*v.z };
    float lam2 = dotf(v, Av);
    f3 v2;
    if (evec_of(a00,a01,a02,a11,a12,a22, lam2, &v2)) return v2;
    return v;
}

__device__ __forceinline__ void planarize(uint32_t jb){
    const int JI[5][4] = {{1,2,3,17},{4,5,6,18},{10,11,12,19},{7,8,9,20},{13,14,15,16}};
    #pragma unroll
    for (int f = 0; f < 5; ++f){
        f3 p0 = ldj(jb, JI[f][0]), p1 = ldj(jb, JI[f][1]);
        f3 p2 = ldj(jb, JI[f][2]), p3 = ldj(jb, JI[f][3]);
        f3 c = (p0 + p1 + p2 + p3) * 0.25f;
        f3 d0 = p0 - c, d1 = p1 - c, d2 = p2 - c, d3 = p3 - c;
        float a00 = d0.x*d0.x + d1.x*d1.x + d2.x*d2.x + d3.x*d3.x;
        float a01 = d0.x*d0.y + d1.x*d1.y + d2.x*d2.y + d3.x*d3.y;
        float a02 = d0.x*d0.z + d1.x*d1.z + d2.x*d2.z + d3.x*d3.z;
        float a11 = d0.y*d0.y + d1.y*d1.y + d2.y*d2.y + d3.y*d3.y;
        float a12 = d0.y*d0.z + d1.y*d1.z + d2.y*d2.z + d3.y*d3.z;
        float a22 = d0.z*d0.z + d1.z*d1.z + d2.z*d2.z + d3.z*d3.z;
        f3 n = min_evec(a00, a01, a02, a11, a12, a22);
        float nd = dotf(n, c);
        float t;
        t = dotf(p0, n) - nd; stj(jb, JI[f][0], p0 - n*t);
        t = dotf(p1, n) - nd; stj(jb, JI[f][1], p1 - n*t);
        t = dotf(p2, n) - nd; stj(jb, JI[f][2], p2 - n*t);
        t = dotf(p3, n) - nd; stj(jb, JI[f][3], p3 - n*t);
    }
}

__device__ __forceinline__ void abduction(uint32_t jb){
    const int   MCPc[5] = {1, 4, 10, 7, 13};
    const int   PIPc[5] = {2, 5, 11, 8, 14};
    const int   CH[5][3] = {{2,3,17},{5,6,18},{11,12,19},{8,9,20},{14,15,16}};
    // cos/sin of RECTIFY angles (constants)
    const float RC[5] = {0.98219260f, 0.99115527f, 0.98890519f, 0.99939801f, 1.0f};
    const float RS[5] = {0.18787680f, 0.13270736f, -0.14854818f, 0.03469304f, 0.0f};
    const float angleP = 0.34906585f;   // pi/9
    #pragma unroll
    for (int i = 0; i < 5; ++i){
        f3 palm = palm_norm(jb, i);
        f3 mcp = ldj(jb, MCPc[i]);
        f3 pip = ldj(jb, PIPc[i]);
        float vd   = -dotf(mcp, palm);
        float dist = dotf(pip, palm) + vd;
        f3 projpip = pip - palm * dist;
        f3 mp = mcp - pip;
        float dis  = sqrtf(dotf(mp, mp));
        f3 pm = projpip - mcp;
        float flex = sqrtf(dotf(pm, pm)) / (dis + EPSF);
        flex = (flex < 0.3f) ? 0.0f : flex;
        f3 wristmcp = unitv(mcp - ldj(jb, 0));
        f3 mcpproj  = unitv(projpip - mcp);
        f3 mcppip   = unitv(pip - mcp);
        // acos(clip(d)) > 1.57  <=>  clip(d) < cos(1.57)
        bool overflex = clip1(dotf(wristmcp, mcppip)) < 7.9632671e-4f;
        float pn  = sqrtf(dotf(palm,palm)) + EPSF;
        float pni = 1.0f / pn;
        mat3 Rr = rodrigues(palm.x*pni, palm.y*pni, palm.z*pni, RC[i], RS[i]);
        f3 rect = mmul(Rr, wristmcp);
        float ang = acosf(clip1(dotf(rect, mcpproj)));
        if (overflex) ang = 0.0f;
        rotsel rs = getrot(angleP, ang, flex, palm, mcpproj, wristmcp);
        #pragma unroll
        for (int k = 0; k < 3; ++k){
            int ch = CH[i][k];
            f3 v = ldj(jb, ch) - mcp;
            stj(jb, ch, applyrot(rs, v) + mcp);
        }
    }
}

__device__ __forceinline__ void plane_rotation(uint32_t jb){
    const int MCPc[4] = {1, 4, 10, 7};
    const int PIPc[4] = {2, 5, 11, 8};
    const int DIPc[4] = {3, 6, 12, 9};
    const int REST[4][2] = {{3,17},{6,18},{12,19},{9,20}};
    const float angleN = 0.34906585f;   // pi/9
    #pragma unroll
    for (int i = 0; i < 4; ++i){
        f3 mcp = ldj(jb, MCPc[i]);
        f3 pip = ldj(jb, PIPc[i]);
        f3 dip = ldj(jb, DIPc[i]);
        f3 mcppip = unitv(pip - mcp);
        f3 pipdip = unitv(dip - pip);
        bool maskline = fabsf(dotf(mcppip, pipdip)) > 0.95f;
        f3 cdir = unitv(crossf(mcppip, pipdip));
        f3 wm   = unitv(mcp - ldj(jb, 0));
        f3 stdv = unitv(crossf(wm, palm_norm(jb, i)));
        float ang = acosf(clip1(dotf(cdir, stdv)));
        if (maskline) ang = 0.0f;
        rotsel rs = getrot(angleN, ang, 1.0f, mcppip, cdir, stdv);
        f3 pivot = pip;   // PR child[0] == PIP, unmodified
        #pragma unroll
        for (int k = 0; k < 2; ++k){
            int ch = REST[i][k];
            f3 v = ldj(jb, ch) - pivot;
            stj(jb, ch, applyrot(rs, v) + pivot);
        }
    }
}

__global__ void __launch_bounds__(BLOCK, 6)
hand_legitimize_kernel(const float* __restrict__ in, float* __restrict__ out, int N){
    __shared__ float s[BLOCK * FPH];
    const int tid = threadIdx.x;
    const int base = blockIdx.x * (BLOCK * FPH);
    const int total = N * FPH;

    // cooperative coalesced load
    #pragma unroll
    for (int k = tid; k < BLOCK * FPH; k += BLOCK){
        int g = base + k;
        s[k] = (g < total) ? in[g] : 0.0f;
    }
    __syncthreads();

    const int h = blockIdx.x * BLOCK + tid;
    if (h < N){
        uint32_t jb = smem_u32(s) + (uint32_t)tid * (FPH * 4u);
        planarize(jb);
        abduction(jb);
        plane_rotation(jb);
        planarize(jb);
    }
    __syncthreads();

    // cooperative coalesced store
    #pragma unroll
    for (int k = tid; k < BLOCK * FPH; k += BLOCK){
        int g = base + k;
        if (g < total) out[g] = s[k];
    }
}

} // namespace

extern "C" void kernel_launch(void* const* d_in, const int* in_sizes, int n_in,
                              void* d_out, int out_size){
    const float* joints = (const float*)d_in[0];
    float* out = (float*)d_out;
    int N = in_sizes[0] / FPH;
    int blocks = (N + BLOCK - 1) / BLOCK;
    hand_legitimize_kernel<<<blocks, BLOCK>>>(joints, out, N);
}